// round 5
// baseline (speedup 1.0000x reference)
#include <cuda_runtime.h>
#include <cuda_bf16.h>
#include <math.h>
#include <stdint.h>

// Problem constants
#define NN 13
#define BB 2
#define TT 2048
#define DD 1024
#define ROW_F4 (DD / 4)          // 256 float4 per row
#define THREADS 256
#define EPS 1.1920928955078125e-07f   // FLT_EPSILON

// smem: s_part[NN][256] float2 (26624 B) + s_logit[NN] + s_al[NN]
__global__ __launch_bounds__(THREADS, 6)
void attn_res_block_kernel(const float4* __restrict__ V,
                           const float4* __restrict__ rms_w,
                           const float4* __restrict__ w_proj,
                           float4* __restrict__ out)
{
    __shared__ float2 s_part[NN][THREADS];
    __shared__ float  s_logit[NN];
    __shared__ float  s_al[NN];

    const int bt   = blockIdx.x;
    const int tid  = threadIdx.x;
    const int lane = tid & 31;
    const int wid  = tid >> 5;

    // Combined weight for this thread's 4 channels
    float4 rw = rms_w[tid];
    float4 wp = w_proj[tid];
    const float w0 = rw.x * wp.x;
    const float w1 = rw.y * wp.y;
    const float w2 = rw.z * wp.z;
    const float w3 = rw.w * wp.w;

    const float4* gbase = V + (long)bt * ROW_F4 + tid;

    // ---- Phase 1: read 13 rows (DRAM), per-thread partials -> smem.
    // No cross-lane ops here: one STS.64 per row. Loads are independent;
    // ptxas pipelines them for high MLP.
    #pragma unroll
    for (int n = 0; n < NN; n++) {
        float4 x = gbase[(long)n * (BB * TT) * ROW_F4];
        float s1 = x.x * x.x + x.y * x.y + x.z * x.z + x.w * x.w;
        float s2 = x.x * w0  + x.y * w1  + x.z * w2  + x.w * w3;
        s_part[n][tid] = make_float2(s1, s2);
    }
    __syncthreads();

    // ---- Stage 2: parallel row reduction. Warp w handles rows n with n%8==w.
    for (int n = wid; n < NN; n += 8) {
        // 256 float2 per row; each lane sums 8 of them (2x float4 loads of 2 float2)
        const float4* p = reinterpret_cast<const float4*>(&s_part[n][0]);
        float4 a0 = p[lane * 4 + 0];
        float4 a1 = p[lane * 4 + 1];
        float4 a2 = p[lane * 4 + 2];
        float4 a3 = p[lane * 4 + 3];
        float tss = a0.x + a0.z + a1.x + a1.z + a2.x + a2.z + a3.x + a3.z;
        float tdp = a0.y + a0.w + a1.y + a1.w + a2.y + a2.w + a3.y + a3.w;
        #pragma unroll
        for (int off = 16; off > 0; off >>= 1) {
            tss += __shfl_xor_sync(0xFFFFFFFFu, tss, off);
            tdp += __shfl_xor_sync(0xFFFFFFFFu, tdp, off);
        }
        if (lane == 0)
            s_logit[n] = rsqrtf(tss * (1.0f / DD) + EPS) * tdp;
    }
    __syncthreads();

    // ---- Softmax over depth: once, by warp 0.
    if (wid == 0) {
        float l = (lane < NN) ? s_logit[lane] : -INFINITY;
        float mx = l;
        #pragma unroll
        for (int off = 16; off > 0; off >>= 1)
            mx = fmaxf(mx, __shfl_xor_sync(0xFFFFFFFFu, mx, off));
        float e = (lane < NN) ? __expf(l - mx) : 0.f;
        float denom = e;
        #pragma unroll
        for (int off = 16; off > 0; off >>= 1)
            denom += __shfl_xor_sync(0xFFFFFFFFu, denom, off);
        if (lane < NN) s_al[lane] = e / denom;
    }
    __syncthreads();

    // ---- Phase 2: weighted sum; V re-read hits L2 (live set ~30MB << 126MB).
    float a[NN];
    #pragma unroll
    for (int n = 0; n < NN; n++) a[n] = s_al[n];

    float4 o = make_float4(0.f, 0.f, 0.f, 0.f);
    #pragma unroll
    for (int n = 0; n < NN; n++) {
        float4 x = gbase[(long)n * (BB * TT) * ROW_F4];
        o.x += a[n] * x.x;
        o.y += a[n] * x.y;
        o.z += a[n] * x.z;
        o.w += a[n] * x.w;
    }
    out[(long)bt * ROW_F4 + tid] = o;
}

extern "C" void kernel_launch(void* const* d_in, const int* in_sizes, int n_in,
                              void* d_out, int out_size)
{
    const float4* V      = (const float4*)d_in[0];   // [13,2,2048,1024] f32
    const float4* rms_w  = (const float4*)d_in[1];   // [1024] f32
    const float4* w_proj = (const float4*)d_in[2];   // [1024] f32
    float4* out          = (float4*)d_out;           // [2,2048,1024] f32

    attn_res_block_kernel<<<BB * TT, THREADS>>>(V, rms_w, w_proj, out);
}

// round 6
// speedup vs baseline: 1.6373x; 1.6373x over previous
#include <cuda_runtime.h>
#include <cuda_bf16.h>
#include <math.h>
#include <stdint.h>

// Problem constants
#define NN 13
#define BB 2
#define TT 2048
#define DD 1024
#define ROW_F4 (DD / 4)          // 256 float4 per row
#define NTILES (BB * TT)         // 4096
#define THREADS 256
#define GRID 304                 // 2 CTAs per SM (152 SMs on GB300)
#define EPS 1.1920928955078125e-07f   // FLT_EPSILON

// Dynamic smem: 2 buffers x NN rows x 256 float4 = 106496 bytes
#define BUF_F4      (NN * ROW_F4)
#define SMEM_BYTES  (2 * BUF_F4 * 16)

__device__ __forceinline__ void cp_async16(uint32_t smem_addr, const void* gptr) {
    asm volatile("cp.async.cg.shared.global [%0], [%1], 16;\n"
                 :: "r"(smem_addr), "l"(gptr));
}

__global__ __launch_bounds__(THREADS, 2)
void attn_res_block_kernel(const float4* __restrict__ V,
                           const float4* __restrict__ rms_w,
                           const float4* __restrict__ w_proj,
                           float4* __restrict__ out)
{
    extern __shared__ float4 sbuf[];        // [2][NN][ROW_F4]
    __shared__ float s_ss[NN][8];
    __shared__ float s_dp[NN][8];
    __shared__ float s_al[NN];

    const int tid  = threadIdx.x;
    const int lane = tid & 31;
    const int wid  = tid >> 5;

    uint32_t sb_a;
    {
        uint64_t t;
        asm("cvta.to.shared.u64 %0, %1;" : "=l"(t) : "l"((void*)sbuf));
        sb_a = (uint32_t)t;
    }

    // Combined weight for this thread's 4 channels
    float4 rw = rms_w[tid];
    float4 wp = w_proj[tid];
    const float w0 = rw.x * wp.x;
    const float w1 = rw.y * wp.y;
    const float w2 = rw.z * wp.z;
    const float w3 = rw.w * wp.w;

    // Issue all 13 row copies of tile `t` into buffer `p` (this thread's column only)
#define ISSUE_TILE(t, p)                                                     \
    {                                                                        \
        const float4* g = V + (long)(t) * ROW_F4 + tid;                      \
        uint32_t s = sb_a + (uint32_t)((p) * BUF_F4 + tid) * 16u;            \
        _Pragma("unroll")                                                    \
        for (int n = 0; n < NN; n++)                                         \
            cp_async16(s + (uint32_t)n * (ROW_F4 * 16u),                     \
                       (const void*)(g + (long)n * (NTILES * ROW_F4)));      \
        asm volatile("cp.async.commit_group;\n");                            \
    }

    int tile = blockIdx.x;
    int p = 0;

    // Prologue: loads for first tile in flight immediately.
    ISSUE_TILE(tile, 0)

    while (tile < NTILES) {
        const int nxt = tile + GRID;

        if (nxt < NTILES) {
            ISSUE_TILE(nxt, p ^ 1)                       // prefetch next tile
            asm volatile("cp.async.wait_group 1;\n" ::: "memory"); // cur done
        } else {
            asm volatile("cp.async.wait_group 0;\n" ::: "memory");
        }

        // ---- Phase 1: rows -> registers, per-row partials + warp reduce.
        // (Each thread reads only bytes its own cp.async wrote: no barrier.)
        const float4* cur = sbuf + p * BUF_F4;
        float4 v[NN];
        #pragma unroll
        for (int n = 0; n < NN; n++) {
            float4 x = cur[n * ROW_F4 + tid];
            v[n] = x;
            float s1 = x.x * x.x + x.y * x.y + x.z * x.z + x.w * x.w;
            float s2 = x.x * w0  + x.y * w1  + x.z * w2  + x.w * w3;
            #pragma unroll
            for (int off = 16; off > 0; off >>= 1) {
                s1 += __shfl_xor_sync(0xFFFFFFFFu, s1, off);
                s2 += __shfl_xor_sync(0xFFFFFFFFu, s2, off);
            }
            if (lane == 0) { s_ss[n][wid] = s1; s_dp[n][wid] = s2; }
        }
        __syncthreads();

        // ---- Softmax over depth: once, by warp 0.
        if (wid == 0) {
            float l = -INFINITY;
            if (lane < NN) {
                float tss = 0.f, tdp = 0.f;
                #pragma unroll
                for (int k = 0; k < 8; k++) { tss += s_ss[lane][k]; tdp += s_dp[lane][k]; }
                l = rsqrtf(tss * (1.0f / DD) + EPS) * tdp;
            }
            float mx = l;
            #pragma unroll
            for (int off = 16; off > 0; off >>= 1)
                mx = fmaxf(mx, __shfl_xor_sync(0xFFFFFFFFu, mx, off));
            float e = (lane < NN) ? __expf(l - mx) : 0.f;
            float denom = e;
            #pragma unroll
            for (int off = 16; off > 0; off >>= 1)
                denom += __shfl_xor_sync(0xFFFFFFFFu, denom, off);
            if (lane < NN) s_al[lane] = e / denom;
        }
        __syncthreads();

        // ---- Phase 2: weighted sum from registers, store.
        float4 o = make_float4(0.f, 0.f, 0.f, 0.f);
        #pragma unroll
        for (int n = 0; n < NN; n++) {
            float an = s_al[n];
            o.x += an * v[n].x;
            o.y += an * v[n].y;
            o.z += an * v[n].z;
            o.w += an * v[n].w;
        }
        out[(long)tile * ROW_F4 + tid] = o;

        // Protect s_ss/s_dp/s_al (and warp skew) before next iteration reuses them.
        __syncthreads();

        tile = nxt;
        p ^= 1;
    }
#undef ISSUE_TILE
}

extern "C" void kernel_launch(void* const* d_in, const int* in_sizes, int n_in,
                              void* d_out, int out_size)
{
    const float4* V      = (const float4*)d_in[0];   // [13,2,2048,1024] f32
    const float4* rms_w  = (const float4*)d_in[1];   // [1024] f32
    const float4* w_proj = (const float4*)d_in[2];   // [1024] f32
    float4* out          = (float4*)d_out;           // [2,2048,1024] f32

    cudaFuncSetAttribute(attn_res_block_kernel,
                         cudaFuncAttributeMaxDynamicSharedMemorySize, SMEM_BYTES);

    attn_res_block_kernel<<<GRID, THREADS, SMEM_BYTES>>>(V, rms_w, w_proj, out);
}

// round 7
// speedup vs baseline: 1.7890x; 1.0926x over previous
#include <cuda_runtime.h>
#include <cuda_bf16.h>
#include <math.h>
#include <stdint.h>

// Problem constants
#define NN 13
#define BB 2
#define TT 2048
#define DD 1024
#define ROW_F4 (DD / 4)          // 256 float4 per row
#define NTILES (BB * TT)         // 4096
#define THREADS 256
#define GRID 304                 // 2 CTAs per SM
#define EPS 1.1920928955078125e-07f   // FLT_EPSILON

// Dynamic smem: 2 row buffers x NN x 256 float4 = 106496 B
#define BUF_F4      (NN * ROW_F4)
#define SMEM_BYTES  (2 * BUF_F4 * 16)

__device__ __forceinline__ void cp_async16(uint32_t smem_addr, const void* gptr) {
    asm volatile("cp.async.cg.shared.global [%0], [%1], 16;\n"
                 :: "r"(smem_addr), "l"(gptr) : "memory");
}

__global__ __launch_bounds__(THREADS, 2)
void attn_res_block_kernel(const float4* __restrict__ V,
                           const float4* __restrict__ rms_w,
                           const float4* __restrict__ w_proj,
                           float4* __restrict__ out)
{
    extern __shared__ float4 sbuf[];            // [2][NN][ROW_F4]
    __shared__ float2 s_part[NN][64];           // 4-lane group partials
    __shared__ float  s_logit[NN];

    const int tid  = threadIdx.x;
    const int lane = tid & 31;
    const int wid  = tid >> 5;

    uint32_t sb_a;
    {
        uint64_t t;
        asm("cvta.to.shared.u64 %0, %1;" : "=l"(t) : "l"((void*)sbuf));
        sb_a = (uint32_t)t;
    }

    // Combined weight (rms_weight * w_proj) for this thread's 4 channels
    float4 rw = rms_w[tid];
    float4 wp = w_proj[tid];
    const float w0 = rw.x * wp.x;
    const float w1 = rw.y * wp.y;
    const float w2 = rw.z * wp.z;
    const float w3 = rw.w * wp.w;

#define ISSUE_TILE(t, pbuf)                                                  \
    {                                                                        \
        const float4* g = V + (long)(t) * ROW_F4 + tid;                      \
        uint32_t s = sb_a + (uint32_t)((pbuf) * BUF_F4 + tid) * 16u;         \
        _Pragma("unroll")                                                    \
        for (int n = 0; n < NN; n++)                                         \
            cp_async16(s + (uint32_t)n * (ROW_F4 * 16u),                     \
                       (const void*)(g + (long)n * (NTILES * ROW_F4)));      \
        asm volatile("cp.async.commit_group;\n" ::: "memory");               \
    }

    int tile = blockIdx.x;
    int p = 0;

    // Prologue: two tiles in flight.
    ISSUE_TILE(tile, 0)
    if (tile + GRID < NTILES) ISSUE_TILE(tile + GRID, 1)

    while (tile < NTILES) {
        // Wait for current tile (keep next tile's group flying if it exists).
        if (tile + GRID < NTILES)
            asm volatile("cp.async.wait_group 1;\n" ::: "memory");
        else
            asm volatile("cp.async.wait_group 0;\n" ::: "memory");

        // ---- Phase 1: rows -> registers; cheap partial reduce (2 shuffles).
        // Each thread reads only bytes its own cp.async wrote: no barrier.
        const float4* cur = sbuf + p * BUF_F4;
        float4 v[NN];
        #pragma unroll
        for (int n = 0; n < NN; n++) {
            float4 x = cur[n * ROW_F4 + tid];
            v[n] = x;
            float s1 = x.x * x.x + x.y * x.y + x.z * x.z + x.w * x.w;
            float s2 = x.x * w0  + x.y * w1  + x.z * w2  + x.w * w3;
            s1 += __shfl_xor_sync(0xFFFFFFFFu, s1, 16);
            s2 += __shfl_xor_sync(0xFFFFFFFFu, s2, 16);
            s1 += __shfl_xor_sync(0xFFFFFFFFu, s1, 8);
            s2 += __shfl_xor_sync(0xFFFFFFFFu, s2, 8);
            if (lane < 8) s_part[n][wid * 8 + lane] = make_float2(s1, s2);
        }

        // Buffer p consumed into registers -> refill it with tile i+2 NOW,
        // so ~2 tiles stay in DRAM flight during the compute tail.
        if (tile + 2 * GRID < NTILES) ISSUE_TILE(tile + 2 * GRID, p)

        __syncthreads();   // B1: s_part complete

        // ---- Stage 2: finish row reductions (<=2 rows per warp).
        for (int n = wid; n < NN; n += 8) {
            float4 a = reinterpret_cast<const float4*>(&s_part[n][0])[lane];
            float tss = a.x + a.z;
            float tdp = a.y + a.w;
            #pragma unroll
            for (int off = 16; off > 0; off >>= 1) {
                tss += __shfl_xor_sync(0xFFFFFFFFu, tss, off);
                tdp += __shfl_xor_sync(0xFFFFFFFFu, tdp, off);
            }
            if (lane == 0)
                s_logit[n] = rsqrtf(tss * (1.0f / DD) + EPS) * tdp;
        }

        __syncthreads();   // B2: s_logit complete

        // ---- Softmax: per-warp (lane n holds logit n), no extra barrier.
        float lv = (lane < NN) ? s_logit[lane] : -INFINITY;
        float mx = lv;
        #pragma unroll
        for (int off = 16; off > 0; off >>= 1)
            mx = fmaxf(mx, __shfl_xor_sync(0xFFFFFFFFu, mx, off));
        float e = (lane < NN) ? __expf(lv - mx) : 0.f;
        float sm = e;
        #pragma unroll
        for (int off = 16; off > 0; off >>= 1)
            sm += __shfl_xor_sync(0xFFFFFFFFu, sm, off);
        const float av = e * (1.0f / sm);     // alpha for depth=lane

        // ---- Phase 2: weighted sum from registers; alpha via shuffle bcast.
        float4 o = make_float4(0.f, 0.f, 0.f, 0.f);
        #pragma unroll
        for (int n = 0; n < NN; n++) {
            float an = __shfl_sync(0xFFFFFFFFu, av, n);
            o.x += an * v[n].x;
            o.y += an * v[n].y;
            o.z += an * v[n].z;
            o.w += an * v[n].w;
        }
        out[(long)tile * ROW_F4 + tid] = o;

        tile += GRID;
        p ^= 1;
    }
#undef ISSUE_TILE
}

extern "C" void kernel_launch(void* const* d_in, const int* in_sizes, int n_in,
                              void* d_out, int out_size)
{
    const float4* V      = (const float4*)d_in[0];   // [13,2,2048,1024] f32
    const float4* rms_w  = (const float4*)d_in[1];   // [1024] f32
    const float4* w_proj = (const float4*)d_in[2];   // [1024] f32
    float4* out          = (float4*)d_out;           // [2,2048,1024] f32

    cudaFuncSetAttribute(attn_res_block_kernel,
                         cudaFuncAttributeMaxDynamicSharedMemorySize, SMEM_BYTES);

    attn_res_block_kernel<<<GRID, THREADS, SMEM_BYTES>>>(V, rms_w, w_proj, out);
}

// round 8
// speedup vs baseline: 1.8197x; 1.0172x over previous
#include <cuda_runtime.h>
#include <cuda_bf16.h>
#include <math.h>
#include <stdint.h>

// Problem constants
#define NN 13
#define BB 2
#define TT 2048
#define DD 1024
#define ROW_F4 (DD / 4)          // 256 float4 per row
#define NTILES (BB * TT)         // 4096
#define THREADS 256
#define GRID 304                 // 2 CTAs per SM
#define EPS 1.1920928955078125e-07f   // FLT_EPSILON

// Dynamic smem: 2 row buffers x NN x 256 float4 = 106496 B
#define BUF_F4      (NN * ROW_F4)
#define SMEM_BYTES  (2 * BUF_F4 * 16)

__device__ __forceinline__ void cp_async16(uint32_t smem_addr, const void* gptr) {
    asm volatile("cp.async.cg.shared.global [%0], [%1], 16;\n"
                 :: "r"(smem_addr), "l"(gptr) : "memory");
}

__global__ __launch_bounds__(THREADS, 2)
void attn_res_block_kernel(const float4* __restrict__ V,
                           const float4* __restrict__ rms_w,
                           const float4* __restrict__ w_proj,
                           float4* __restrict__ out)
{
    extern __shared__ float4 sbuf[];            // [2][NN][ROW_F4]
    __shared__ float s_logit[NN];

    const int tid  = threadIdx.x;
    const int lane = tid & 31;
    const int wid  = tid >> 5;

    uint32_t sb_a;
    {
        uint64_t t;
        asm("cvta.to.shared.u64 %0, %1;" : "=l"(t) : "l"((void*)sbuf));
        sb_a = (uint32_t)t;
    }

    // Lane-indexed combined weight (rms_weight * w_proj), held in registers
    // for the whole persistent loop. Phase-1 row view: thread `lane` covers
    // float4 channels k*32+lane, k=0..7.
    float4 cw[8];
    #pragma unroll
    for (int k = 0; k < 8; k++) {
        float4 a = rms_w[k * 32 + lane];
        float4 b = w_proj[k * 32 + lane];
        cw[k] = make_float4(a.x * b.x, a.y * b.y, a.z * b.z, a.w * b.w);
    }

#define ISSUE_TILE(t, pbuf)                                                  \
    {                                                                        \
        const float4* g = V + (long)(t) * ROW_F4 + tid;                      \
        uint32_t s = sb_a + (uint32_t)((pbuf) * BUF_F4 + tid) * 16u;         \
        _Pragma("unroll")                                                    \
        for (int n = 0; n < NN; n++)                                         \
            cp_async16(s + (uint32_t)n * (ROW_F4 * 16u),                     \
                       (const void*)(g + (long)n * (NTILES * ROW_F4)));      \
        asm volatile("cp.async.commit_group;\n" ::: "memory");               \
    }

    int tile = blockIdx.x;
    int p = 0;

    // Prologue: two tiles in flight.
    ISSUE_TILE(tile, 0)
    if (tile + GRID < NTILES) ISSUE_TILE(tile + GRID, 1)

    while (tile < NTILES) {
        if (tile + GRID < NTILES)
            asm volatile("cp.async.wait_group 1;\n" ::: "memory");
        else
            asm volatile("cp.async.wait_group 0;\n" ::: "memory");
        __syncthreads();   // B0: all threads' groups for tile i visible to all

        const float4* cur = sbuf + p * BUF_F4;

        // ---- Phase 1 (row-mapped): warp w owns rows w and w+8.
        // Strided conflict-free LDS; full dual reduce in-warp -> logit.
        #pragma unroll
        for (int rep = 0; rep < 2; rep++) {
            const int r = wid + rep * 8;
            if (r < NN) {
                float tss = 0.f, tdp = 0.f;
                #pragma unroll
                for (int k = 0; k < 8; k++) {
                    float4 x = cur[r * ROW_F4 + k * 32 + lane];
                    tss = fmaf(x.x, x.x, fmaf(x.y, x.y, fmaf(x.z, x.z, fmaf(x.w, x.w, tss))));
                    tdp = fmaf(x.x, cw[k].x, fmaf(x.y, cw[k].y, fmaf(x.z, cw[k].z, fmaf(x.w, cw[k].w, tdp))));
                }
                #pragma unroll
                for (int off = 16; off > 0; off >>= 1) {
                    tss += __shfl_xor_sync(0xFFFFFFFFu, tss, off);
                    tdp += __shfl_xor_sync(0xFFFFFFFFu, tdp, off);
                }
                if (lane == 0)
                    s_logit[r] = rsqrtf(tss * (1.0f / DD) + EPS) * tdp;
            }
        }
        __syncthreads();   // B1: logits visible; phase-1 buffer reads done

        // ---- Softmax: per-warp, redundant (no extra barrier).
        float lv = (lane < NN) ? s_logit[lane] : -INFINITY;
        float mx = lv;
        #pragma unroll
        for (int off = 16; off > 0; off >>= 1)
            mx = fmaxf(mx, __shfl_xor_sync(0xFFFFFFFFu, mx, off));
        float e = (lane < NN) ? __expf(lv - mx) : 0.f;
        float sm = e;
        #pragma unroll
        for (int off = 16; off > 0; off >>= 1)
            sm += __shfl_xor_sync(0xFFFFFFFFu, sm, off);
        const float av = e * (1.0f / sm);     // alpha for depth = lane

        // ---- Phase 2 (column-mapped): weighted sum; alphas via shuffle bcast.
        float4 o = make_float4(0.f, 0.f, 0.f, 0.f);
        #pragma unroll
        for (int n = 0; n < NN; n++) {
            float4 x = cur[n * ROW_F4 + tid];
            float an = __shfl_sync(0xFFFFFFFFu, av, n);
            o.x = fmaf(an, x.x, o.x);
            o.y = fmaf(an, x.y, o.y);
            o.z = fmaf(an, x.z, o.z);
            o.w = fmaf(an, x.w, o.w);
        }
        out[(long)tile * ROW_F4 + tid] = o;

        // Refill buffer p with tile i+2. Safe without a barrier: cell [n][tid]
        // is written by this thread's cp.async and was read (phase 2) by this
        // thread only; phase-1 cross-thread reads were fenced by B1.
        if (tile + 2 * GRID < NTILES) ISSUE_TILE(tile + 2 * GRID, p)

        tile += GRID;
        p ^= 1;
    }
#undef ISSUE_TILE
}

extern "C" void kernel_launch(void* const* d_in, const int* in_sizes, int n_in,
                              void* d_out, int out_size)
{
    const float4* V      = (const float4*)d_in[0];   // [13,2,2048,1024] f32
    const float4* rms_w  = (const float4*)d_in[1];   // [1024] f32
    const float4* w_proj = (const float4*)d_in[2];   // [1024] f32
    float4* out          = (float4*)d_out;           // [2,2048,1024] f32

    cudaFuncSetAttribute(attn_res_block_kernel,
                         cudaFuncAttributeMaxDynamicSharedMemorySize, SMEM_BYTES);

    attn_res_block_kernel<<<GRID, THREADS, SMEM_BYTES>>>(V, rms_w, w_proj, out);
}